// round 3
// baseline (speedup 1.0000x reference)
#include <cuda_runtime.h>

#define NCL 10
#define D 64
#define NSLOT 4096

__device__ float g_cc[NCL * D];

// ---------- helpers ----------
__device__ __forceinline__ float dot64_gs(const float* __restrict__ w,
                                          const float* __restrict__ xs) {
    float s = 0.f;
#pragma unroll
    for (int c = 0; c < 16; c++) {
        float4 a = __ldg(reinterpret_cast<const float4*>(w) + c);
        float4 b = reinterpret_cast<const float4*>(xs)[c];
        s = fmaf(a.x, b.x, s); s = fmaf(a.y, b.y, s);
        s = fmaf(a.z, b.z, s); s = fmaf(a.w, b.w, s);
    }
    return s;
}

__device__ __forceinline__ float dot64_ss(const float* xs, const float* ys) {
    float s = 0.f;
#pragma unroll
    for (int c = 0; c < 16; c++) {
        float4 a = reinterpret_cast<const float4*>(xs)[c];
        float4 b = reinterpret_cast<const float4*>(ys)[c];
        s = fmaf(a.x, b.x, s); s = fmaf(a.y, b.y, s);
        s = fmaf(a.z, b.z, s); s = fmaf(a.w, b.w, s);
    }
    return s;
}

__device__ __forceinline__ float dot128_gs(const float* __restrict__ w,
                                           const float* __restrict__ xs) {
    float s = 0.f;
#pragma unroll
    for (int c = 0; c < 32; c++) {
        float4 a = __ldg(reinterpret_cast<const float4*>(w) + c);
        float4 b = reinterpret_cast<const float4*>(xs)[c];
        s = fmaf(a.x, b.x, s); s = fmaf(a.y, b.y, s);
        s = fmaf(a.z, b.z, s); s = fmaf(a.w, b.w, s);
    }
    return s;
}

// LayerNorm over last dim (64) for 10 rows, 640 threads, 2 warps per row.
__device__ __forceinline__ void ln640(float x, const float* __restrict__ g,
                                      const float* __restrict__ b,
                                      float* ln_out, float* redS, float* redQ,
                                      int t, int n, int i, int w) {
    float s1 = x, s2 = x * x;
#pragma unroll
    for (int o = 16; o; o >>= 1) {
        s1 += __shfl_xor_sync(0xffffffffu, s1, o);
        s2 += __shfl_xor_sync(0xffffffffu, s2, o);
    }
    if ((t & 31) == 0) { redS[w] = s1; redQ[w] = s2; }
    __syncthreads();
    float sum = redS[2 * n] + redS[2 * n + 1];
    float sq  = redQ[2 * n] + redQ[2 * n + 1];
    float m = sum * (1.f / 64.f);
    float var = sq * (1.f / 64.f) - m * m;
    ln_out[t] = (x - m) * rsqrtf(var + 1e-5f) * g[i] + b[i];
    __syncthreads();
}

// ---------- phase 1: iterative slot attention on one block ----------
__global__ void __launch_bounds__(640)
phase1_kernel(const float* __restrict__ cc0,
              const float* __restrict__ Wk, const float* __restrict__ bk,
              const float* __restrict__ Wq, const float* __restrict__ bq,
              const float* __restrict__ Wv, const float* __restrict__ bv,
              const float* __restrict__ cc_g, const float* __restrict__ cc_b,
              const float* __restrict__ W_ih, const float* __restrict__ W_hh,
              const float* __restrict__ b_ih, const float* __restrict__ b_hh,
              const float* __restrict__ ln_g, const float* __restrict__ ln_b,
              const float* __restrict__ W1, const float* __restrict__ b1,
              const float* __restrict__ W2, const float* __restrict__ b2) {
    __shared__ float cc_s[640], k_s[640], v_s[640], q_s[640], ln_s[640], upd_s[640];
    __shared__ float hid_s[1280];
    __shared__ float attn_s[112];
    __shared__ float redS[20], redQ[20];

    const int t = threadIdx.x;
    const int n = t >> 6;
    const int i = t & 63;
    const int w = t >> 5;

    cc_s[t] = cc0[t];
    __syncthreads();

    k_s[t] = dot64_gs(Wk + i * 64, cc_s + n * 64) + bk[i];
    v_s[t] = dot64_gs(Wv + i * 64, cc_s + n * 64) + bv[i];
    __syncthreads();

    const float temp = 0.125f;  // 64^-0.5

    for (int it = 0; it < 3; it++) {
        // ln over cc -> ln_s
        float ccx = cc_s[t];
        ln640(ccx, cc_g, cc_b, ln_s, redS, redQ, t, n, i, w);

        // q
        q_s[t] = dot64_gs(Wq + i * 64, ln_s + n * 64) + bq[i];
        __syncthreads();

        // attention scores [n, m] = k[n] . q[m] * temp
        if (t < 100) {
            int nn = t / 10, mm = t % 10;
            attn_s[nn * 10 + mm] = temp * dot64_ss(k_s + nn * 64, q_s + mm * 64);
        }
        __syncthreads();

        // softmax over n (axis 0) per column m, then +EPS
        if (t < 10) {
            float mx = -1e30f;
#pragma unroll
            for (int nn = 0; nn < 10; nn++) mx = fmaxf(mx, attn_s[nn * 10 + t]);
            float e[10];
            float sum = 0.f;
#pragma unroll
            for (int nn = 0; nn < 10; nn++) {
                e[nn] = expf(attn_s[nn * 10 + t] - mx);
                sum += e[nn];
            }
            float inv = 1.f / sum;
#pragma unroll
            for (int nn = 0; nn < 10; nn++)
                attn_s[nn * 10 + t] = e[nn] * inv + 1e-8f;
        }
        __syncthreads();

        // renormalize rows (axis -1 = m) per row n
        if (t < 10) {
            float sum = 0.f;
#pragma unroll
            for (int mm = 0; mm < 10; mm++) sum += attn_s[t * 10 + mm];
            float inv = 1.f / sum;
#pragma unroll
            for (int mm = 0; mm < 10; mm++) attn_s[t * 10 + mm] *= inv;
        }
        __syncthreads();

        // updates = attn @ v
        float u = 0.f;
#pragma unroll
        for (int mm = 0; mm < 10; mm++)
            u = fmaf(attn_s[n * 10 + mm], v_s[mm * 64 + i], u);
        upd_s[t] = u;
        __syncthreads();

        // GRU cell
        float ir = dot64_gs(W_ih + i * 64,          upd_s + n * 64) + b_ih[i];
        float iz = dot64_gs(W_ih + (64 + i) * 64,   upd_s + n * 64) + b_ih[64 + i];
        float in_ = dot64_gs(W_ih + (128 + i) * 64, upd_s + n * 64) + b_ih[128 + i];
        float hr = dot64_gs(W_hh + i * 64,          cc_s + n * 64) + b_hh[i];
        float hz = dot64_gs(W_hh + (64 + i) * 64,   cc_s + n * 64) + b_hh[64 + i];
        float hn = dot64_gs(W_hh + (128 + i) * 64,  cc_s + n * 64) + b_hh[128 + i];
        float r = 1.f / (1.f + expf(-(ir + hr)));
        float z = 1.f / (1.f + expf(-(iz + hz)));
        float nn_ = tanhf(in_ + r * hn);
        float ccn = (1.f - z) * nn_ + z * ccx;
        __syncthreads();   // all GRU reads of cc_s done
        cc_s[t] = ccn;
        __syncthreads();

        // residual MLP
        ln640(ccn, ln_g, ln_b, ln_s, redS, redQ, t, n, i, w);
        float h0 = fmaxf(dot64_gs(W1 + i * 64,        ln_s + n * 64) + b1[i], 0.f);
        float h1 = fmaxf(dot64_gs(W1 + (64 + i) * 64, ln_s + n * 64) + b1[64 + i], 0.f);
        hid_s[n * 128 + i] = h0;
        hid_s[n * 128 + 64 + i] = h1;
        __syncthreads();
        float d2 = dot128_gs(W2 + i * 128, hid_s + n * 128) + b2[i];
        cc_s[t] = ccn + d2;
        __syncthreads();
    }

    g_cc[t] = cc_s[t];
}

// ---------- phase 2: per-slot MLP + max over clusters ----------
__device__ __forceinline__ void cp16(void* dst_smem, const void* src) {
    unsigned d = (unsigned)__cvta_generic_to_shared(dst_smem);
    asm volatile("cp.async.cg.shared.global [%0], [%1], 16;\n" ::"r"(d), "l"(src));
}

__global__ void __launch_bounds__(64)
phase2_kernel(const float* __restrict__ Wa, const float* __restrict__ ba,
              const float* __restrict__ Wb, const float* __restrict__ bb,
              float* __restrict__ out) {
    __shared__ float A[64 * 68];   // stride-68 padded: bank-conflict-free row reads
    __shared__ float B[64 * 68];
    __shared__ float ccs[640];
    __shared__ float hs[640];

    const int s = blockIdx.x;
    const int t = threadIdx.x;
    const float* srcA = Wa + (size_t)s * 4096;
    const float* srcB = Wb + (size_t)s * 4096;

    // prefetch A (group 0) and B (group 1)
#pragma unroll
    for (int k = 0; k < 16; k++) {
        int f = t + 64 * k;
        int dst = (f >> 4) * 68 + (f & 15) * 4;
        cp16(&A[dst], srcA + f * 4);
    }
    asm volatile("cp.async.commit_group;\n" ::: "memory");
#pragma unroll
    for (int k = 0; k < 16; k++) {
        int f = t + 64 * k;
        int dst = (f >> 4) * 68 + (f & 15) * 4;
        cp16(&B[dst], srcB + f * 4);
    }
    asm volatile("cp.async.commit_group;\n" ::: "memory");

#pragma unroll
    for (int k = 0; k < 10; k++) ccs[t + 64 * k] = g_cc[t + 64 * k];
    float ba_i = __ldg(ba + (size_t)s * 64 + t);
    float bb_i = __ldg(bb + (size_t)s * 64 + t);

    asm volatile("cp.async.wait_group 1;\n" ::: "memory");  // A ready
    __syncthreads();

    // stage 1: h[n, t] = relu(Wa[t,:] . cc[n,:] + ba[t])
    float acc[10];
#pragma unroll
    for (int nn = 0; nn < 10; nn++) acc[nn] = 0.f;
#pragma unroll
    for (int c = 0; c < 16; c++) {
        float4 a = *reinterpret_cast<const float4*>(&A[t * 68 + c * 4]);
#pragma unroll
        for (int nn = 0; nn < 10; nn++) {
            float4 x = *reinterpret_cast<const float4*>(&ccs[nn * 64 + c * 4]);
            acc[nn] = fmaf(a.x, x.x, acc[nn]);
            acc[nn] = fmaf(a.y, x.y, acc[nn]);
            acc[nn] = fmaf(a.z, x.z, acc[nn]);
            acc[nn] = fmaf(a.w, x.w, acc[nn]);
        }
    }
#pragma unroll
    for (int nn = 0; nn < 10; nn++)
        hs[nn * 64 + t] = fmaxf(acc[nn] + ba_i, 0.f);

    asm volatile("cp.async.wait_group 0;\n" ::: "memory");  // B ready
    __syncthreads();

    // stage 2: out[n, t] = Wb[t,:] . h[n,:]; reduce max over n
#pragma unroll
    for (int nn = 0; nn < 10; nn++) acc[nn] = 0.f;
#pragma unroll
    for (int c = 0; c < 16; c++) {
        float4 b = *reinterpret_cast<const float4*>(&B[t * 68 + c * 4]);
#pragma unroll
        for (int nn = 0; nn < 10; nn++) {
            float4 x = *reinterpret_cast<const float4*>(&hs[nn * 64 + c * 4]);
            acc[nn] = fmaf(b.x, x.x, acc[nn]);
            acc[nn] = fmaf(b.y, x.y, acc[nn]);
            acc[nn] = fmaf(b.z, x.z, acc[nn]);
            acc[nn] = fmaf(b.w, x.w, acc[nn]);
        }
    }
    float mx = acc[0];
#pragma unroll
    for (int nn = 1; nn < 10; nn++) mx = fmaxf(mx, acc[nn]);
    out[(size_t)s * 64 + t] = mx + bb_i;
}

// ---------- launch ----------
extern "C" void kernel_launch(void* const* d_in, const int* in_sizes, int n_in,
                              void* d_out, int out_size) {
    const float* cc0  = (const float*)d_in[0];
    const float* Wk   = (const float*)d_in[1];
    const float* bk   = (const float*)d_in[2];
    const float* Wq   = (const float*)d_in[3];
    const float* bq   = (const float*)d_in[4];
    const float* Wv   = (const float*)d_in[5];
    const float* bv   = (const float*)d_in[6];
    const float* cc_g = (const float*)d_in[7];
    const float* cc_b = (const float*)d_in[8];
    const float* W_ih = (const float*)d_in[9];
    const float* W_hh = (const float*)d_in[10];
    const float* b_ih = (const float*)d_in[11];
    const float* b_hh = (const float*)d_in[12];
    const float* ln_g = (const float*)d_in[13];
    const float* ln_b = (const float*)d_in[14];
    const float* W1   = (const float*)d_in[15];
    const float* b1   = (const float*)d_in[16];
    const float* W2   = (const float*)d_in[17];
    const float* b2   = (const float*)d_in[18];
    const float* Wa   = (const float*)d_in[19];
    const float* ba   = (const float*)d_in[20];
    const float* Wb   = (const float*)d_in[21];
    const float* bb   = (const float*)d_in[22];

    phase1_kernel<<<1, 640>>>(cc0, Wk, bk, Wq, bq, Wv, bv, cc_g, cc_b,
                              W_ih, W_hh, b_ih, b_hh, ln_g, ln_b,
                              W1, b1, W2, b2);
    phase2_kernel<<<NSLOT, 64>>>(Wa, ba, Wb, bb, (float*)d_out);
}

// round 6
// speedup vs baseline: 1.8291x; 1.8291x over previous
#include <cuda_runtime.h>

#define NCL 10
#define D 64
#define NSLOT 4096
#define SP 68          // padded row stride for 64-wide rows
#define SP2 132        // padded row stride for 128-wide rows

__device__ float g_cc[NCL * D];

// ---------- cp.async helper ----------
__device__ __forceinline__ void cp16(void* dst_smem, const void* src) {
    unsigned d = (unsigned)__cvta_generic_to_shared(dst_smem);
    asm volatile("cp.async.cg.shared.global [%0], [%1], 16;\n" ::"r"(d), "l"(src));
}

// ---------- smem dot products (broadcast-friendly, 4 accumulators) ----------
__device__ __forceinline__ float dot64s(const float* __restrict__ w,
                                        const float* __restrict__ x) {
    const float4* W = reinterpret_cast<const float4*>(w);
    const float4* X = reinterpret_cast<const float4*>(x);
    float a0 = 0.f, a1 = 0.f, a2 = 0.f, a3 = 0.f;
#pragma unroll
    for (int c = 0; c < 16; c += 4) {
        float4 p0 = W[c+0], q0 = X[c+0];
        a0 = fmaf(p0.x, q0.x, a0); a0 = fmaf(p0.y, q0.y, a0);
        a0 = fmaf(p0.z, q0.z, a0); a0 = fmaf(p0.w, q0.w, a0);
        float4 p1 = W[c+1], q1 = X[c+1];
        a1 = fmaf(p1.x, q1.x, a1); a1 = fmaf(p1.y, q1.y, a1);
        a1 = fmaf(p1.z, q1.z, a1); a1 = fmaf(p1.w, q1.w, a1);
        float4 p2 = W[c+2], q2 = X[c+2];
        a2 = fmaf(p2.x, q2.x, a2); a2 = fmaf(p2.y, q2.y, a2);
        a2 = fmaf(p2.z, q2.z, a2); a2 = fmaf(p2.w, q2.w, a2);
        float4 p3 = W[c+3], q3 = X[c+3];
        a3 = fmaf(p3.x, q3.x, a3); a3 = fmaf(p3.y, q3.y, a3);
        a3 = fmaf(p3.z, q3.z, a3); a3 = fmaf(p3.w, q3.w, a3);
    }
    return (a0 + a1) + (a2 + a3);
}

__device__ __forceinline__ float dot128s(const float* __restrict__ w,
                                         const float* __restrict__ x) {
    const float4* W = reinterpret_cast<const float4*>(w);
    const float4* X = reinterpret_cast<const float4*>(x);
    float a0 = 0.f, a1 = 0.f, a2 = 0.f, a3 = 0.f;
#pragma unroll
    for (int c = 0; c < 32; c += 4) {
        float4 p0 = W[c+0], q0 = X[c+0];
        a0 = fmaf(p0.x, q0.x, a0); a0 = fmaf(p0.y, q0.y, a0);
        a0 = fmaf(p0.z, q0.z, a0); a0 = fmaf(p0.w, q0.w, a0);
        float4 p1 = W[c+1], q1 = X[c+1];
        a1 = fmaf(p1.x, q1.x, a1); a1 = fmaf(p1.y, q1.y, a1);
        a1 = fmaf(p1.z, q1.z, a1); a1 = fmaf(p1.w, q1.w, a1);
        float4 p2 = W[c+2], q2 = X[c+2];
        a2 = fmaf(p2.x, q2.x, a2); a2 = fmaf(p2.y, q2.y, a2);
        a2 = fmaf(p2.z, q2.z, a2); a2 = fmaf(p2.w, q2.w, a2);
        float4 p3 = W[c+3], q3 = X[c+3];
        a3 = fmaf(p3.x, q3.x, a3); a3 = fmaf(p3.y, q3.y, a3);
        a3 = fmaf(p3.z, q3.z, a3); a3 = fmaf(p3.w, q3.w, a3);
    }
    return (a0 + a1) + (a2 + a3);
}

// ---------- dynamic smem layout (floats) ----------
#define OFF_WIH 0                       // 192 x SP
#define OFF_WHH (OFF_WIH + 192 * SP)    // 192 x SP
#define OFF_WQ  (OFF_WHH + 192 * SP)    //  64 x SP
#define OFF_W1  (OFF_WQ  +  64 * SP)    // 128 x SP
#define OFF_W2  (OFF_W1  + 128 * SP)    //  64 x SP2
#define DYN_FLOATS (OFF_W2 + 64 * SP2)
#define DYN_BYTES  (DYN_FLOATS * 4)

// stage a [rows x 64] row-major matrix into padded smem (stride SP)
__device__ __forceinline__ void stage64(float* dst, const float* __restrict__ src,
                                        int rows, int t) {
    int nq = rows * 16;
    for (int idx = t; idx < nq; idx += 640) {
        int r = idx >> 4, c = idx & 15;
        cp16(&dst[r * SP + c * 4], src + idx * 4);
    }
}
// stage a [64 x 128] matrix into padded smem (stride SP2)
__device__ __forceinline__ void stage128(float* dst, const float* __restrict__ src,
                                         int t) {
    for (int idx = t; idx < 64 * 32; idx += 640) {
        int r = idx >> 5, c = idx & 31;
        cp16(&dst[r * SP2 + c * 4], src + idx * 4);
    }
}

// LayerNorm over i (64) for each n: warp w handles row n=w/2, half h=w&1.
__device__ __forceinline__ void ln_pad(const float* __restrict__ src,
                                       float* __restrict__ dst,
                                       float g_i, float b_i,
                                       float* redS, float* redQ,
                                       int t, int n, int i) {
    int w = t >> 5, lane = t & 31;
    int nw = w >> 1, h = w & 1;
    float xv = src[nw * SP + h * 32 + lane];
    float s1 = xv, s2 = xv * xv;
#pragma unroll
    for (int o = 16; o; o >>= 1) {
        s1 += __shfl_xor_sync(0xffffffffu, s1, o);
        s2 += __shfl_xor_sync(0xffffffffu, s2, o);
    }
    if (lane == 0) { redS[w] = s1; redQ[w] = s2; }
    __syncthreads();
    float sum = redS[2 * n] + redS[2 * n + 1];
    float sq  = redQ[2 * n] + redQ[2 * n + 1];
    float m = sum * (1.f / 64.f);
    float var = sq * (1.f / 64.f) - m * m;
    dst[n * SP + i] = (src[n * SP + i] - m) * rsqrtf(var + 1e-5f) * g_i + b_i;
    __syncthreads();
}

// ---------- phase 1 ----------
__global__ void __launch_bounds__(640)
phase1_kernel(const float* __restrict__ cc0,
              const float* __restrict__ Wk, const float* __restrict__ bk,
              const float* __restrict__ Wq, const float* __restrict__ bq,
              const float* __restrict__ Wv, const float* __restrict__ bv,
              const float* __restrict__ cc_g, const float* __restrict__ cc_b,
              const float* __restrict__ W_ih, const float* __restrict__ W_hh,
              const float* __restrict__ b_ih, const float* __restrict__ b_hh,
              const float* __restrict__ ln_g, const float* __restrict__ ln_b,
              const float* __restrict__ W1, const float* __restrict__ b1,
              const float* __restrict__ W2, const float* __restrict__ b2) {
    extern __shared__ float dyn[];
    __shared__ float cc_s[NCL * SP], k_s[NCL * SP], v_s[NCL * SP];
    __shared__ float q_s[NCL * SP], ln_s[NCL * SP], upd_s[NCL * SP];
    __shared__ float hid_s[NCL * SP2];
    __shared__ float attn_s[112];
    __shared__ float redS[20], redQ[20];

    const int t = threadIdx.x;
    const int i = t / 10;     // output/feature index 0..63
    const int n = t % 10;     // cluster index 0..9

    // preload per-thread constants
    const float bq_i  = __ldg(bq + i);
    const float bih0  = __ldg(b_ih + i);
    const float bih1  = __ldg(b_ih + 64 + i);
    const float bih2  = __ldg(b_ih + 128 + i);
    const float bhh0  = __ldg(b_hh + i);
    const float bhh1  = __ldg(b_hh + 64 + i);
    const float bhh2  = __ldg(b_hh + 128 + i);
    const float b1_0  = __ldg(b1 + i);
    const float b1_1  = __ldg(b1 + 64 + i);
    const float b2_i  = __ldg(b2 + i);
    const float ccg_i = __ldg(cc_g + i);
    const float ccb_i = __ldg(cc_b + i);
    const float lng_i = __ldg(ln_g + i);
    const float lnb_i = __ldg(ln_b + i);

    cc_s[n * SP + i] = cc0[n * 64 + i];

    // transient: stage Wk into WIH region, Wv into WHH region for k/v prologue
    stage64(dyn + OFF_WIH, Wk, 64, t);
    stage64(dyn + OFF_WHH, Wv, 64, t);
    asm volatile("cp.async.commit_group;\ncp.async.wait_group 0;\n" ::: "memory");
    __syncthreads();

    k_s[n * SP + i] = dot64s(dyn + OFF_WIH + i * SP, cc_s + n * SP) + __ldg(bk + i);
    v_s[n * SP + i] = dot64s(dyn + OFF_WHH + i * SP, cc_s + n * SP) + __ldg(bv + i);
    __syncthreads();   // k/v reads of staging region done

    // stage the loop weights (overwrites Wk/Wv regions)
    stage64(dyn + OFF_WIH, W_ih, 192, t);
    stage64(dyn + OFF_WHH, W_hh, 192, t);
    stage64(dyn + OFF_WQ,  Wq,   64, t);
    stage64(dyn + OFF_W1,  W1,  128, t);
    stage128(dyn + OFF_W2, W2, t);
    asm volatile("cp.async.commit_group;\ncp.async.wait_group 0;\n" ::: "memory");
    __syncthreads();

    const float temp = 0.125f;

    for (int it = 0; it < 3; it++) {
        // ln(cc) -> ln_s
        ln_pad(cc_s, ln_s, ccg_i, ccb_i, redS, redQ, t, n, i);

        // q
        q_s[n * SP + i] = dot64s(dyn + OFF_WQ + i * SP, ln_s + n * SP) + bq_i;
        __syncthreads();

        // attention scores [nn, mm]
        if (t < 100) {
            int nn = t / 10, mm = t % 10;
            attn_s[nn * 10 + mm] = temp * dot64s(k_s + nn * SP, q_s + mm * SP);
        }
        __syncthreads();

        // softmax over nn per column mm, +EPS
        if (t < 10) {
            float mx = -1e30f;
#pragma unroll
            for (int nn = 0; nn < 10; nn++) mx = fmaxf(mx, attn_s[nn * 10 + t]);
            float e[10]; float sum = 0.f;
#pragma unroll
            for (int nn = 0; nn < 10; nn++) {
                e[nn] = expf(attn_s[nn * 10 + t] - mx);
                sum += e[nn];
            }
            float inv = 1.f / sum;
#pragma unroll
            for (int nn = 0; nn < 10; nn++)
                attn_s[nn * 10 + t] = e[nn] * inv + 1e-8f;
        }
        __syncthreads();

        // renormalize rows
        if (t < 10) {
            float sum = 0.f;
#pragma unroll
            for (int mm = 0; mm < 10; mm++) sum += attn_s[t * 10 + mm];
            float inv = 1.f / sum;
#pragma unroll
            for (int mm = 0; mm < 10; mm++) attn_s[t * 10 + mm] *= inv;
        }
        __syncthreads();

        // updates = attn @ v
        float u = 0.f;
#pragma unroll
        for (int mm = 0; mm < 10; mm++)
            u = fmaf(attn_s[n * 10 + mm], v_s[mm * SP + i], u);
        upd_s[n * SP + i] = u;
        __syncthreads();

        // GRU cell
        float ccx = cc_s[n * SP + i];
        float ir  = dot64s(dyn + OFF_WIH + i * SP,          upd_s + n * SP) + bih0;
        float iz  = dot64s(dyn + OFF_WIH + (64 + i) * SP,   upd_s + n * SP) + bih1;
        float in_ = dot64s(dyn + OFF_WIH + (128 + i) * SP,  upd_s + n * SP) + bih2;
        float hr  = dot64s(dyn + OFF_WHH + i * SP,          cc_s + n * SP) + bhh0;
        float hz  = dot64s(dyn + OFF_WHH + (64 + i) * SP,   cc_s + n * SP) + bhh1;
        float hn  = dot64s(dyn + OFF_WHH + (128 + i) * SP,  cc_s + n * SP) + bhh2;
        float r = 1.f / (1.f + expf(-(ir + hr)));
        float z = 1.f / (1.f + expf(-(iz + hz)));
        float nn_ = tanhf(in_ + r * hn);
        float ccn = (1.f - z) * nn_ + z * ccx;
        __syncthreads();        // all GRU reads of cc_s done
        cc_s[n * SP + i] = ccn;
        __syncthreads();

        // residual MLP
        ln_pad(cc_s, ln_s, lng_i, lnb_i, redS, redQ, t, n, i);
        float h0 = fmaxf(dot64s(dyn + OFF_W1 + i * SP,        ln_s + n * SP) + b1_0, 0.f);
        float h1 = fmaxf(dot64s(dyn + OFF_W1 + (64 + i) * SP, ln_s + n * SP) + b1_1, 0.f);
        hid_s[n * SP2 + i] = h0;
        hid_s[n * SP2 + 64 + i] = h1;
        __syncthreads();
        float d2 = dot128s(dyn + OFF_W2 + i * SP2, hid_s + n * SP2) + b2_i;
        cc_s[n * SP + i] = ccn + d2;
        __syncthreads();
    }

    g_cc[n * 64 + i] = cc_s[n * SP + i];
}

// ---------- phase 2: per-slot MLP + max over clusters (unchanged) ----------
__global__ void __launch_bounds__(64)
phase2_kernel(const float* __restrict__ Wa, const float* __restrict__ ba,
              const float* __restrict__ Wb, const float* __restrict__ bb,
              float* __restrict__ out) {
    __shared__ float A[64 * 68];
    __shared__ float B[64 * 68];
    __shared__ float ccs[640];
    __shared__ float hs[640];

    const int s = blockIdx.x;
    const int t = threadIdx.x;
    const float* srcA = Wa + (size_t)s * 4096;
    const float* srcB = Wb + (size_t)s * 4096;

#pragma unroll
    for (int k = 0; k < 16; k++) {
        int f = t + 64 * k;
        int dst = (f >> 4) * 68 + (f & 15) * 4;
        cp16(&A[dst], srcA + f * 4);
    }
    asm volatile("cp.async.commit_group;\n" ::: "memory");
#pragma unroll
    for (int k = 0; k < 16; k++) {
        int f = t + 64 * k;
        int dst = (f >> 4) * 68 + (f & 15) * 4;
        cp16(&B[dst], srcB + f * 4);
    }
    asm volatile("cp.async.commit_group;\n" ::: "memory");

#pragma unroll
    for (int k = 0; k < 10; k++) ccs[t + 64 * k] = g_cc[t + 64 * k];
    float ba_i = __ldg(ba + (size_t)s * 64 + t);
    float bb_i = __ldg(bb + (size_t)s * 64 + t);

    asm volatile("cp.async.wait_group 1;\n" ::: "memory");
    __syncthreads();

    float acc[10];
#pragma unroll
    for (int nn = 0; nn < 10; nn++) acc[nn] = 0.f;
#pragma unroll
    for (int c = 0; c < 16; c++) {
        float4 a = *reinterpret_cast<const float4*>(&A[t * 68 + c * 4]);
#pragma unroll
        for (int nn = 0; nn < 10; nn++) {
            float4 x = *reinterpret_cast<const float4*>(&ccs[nn * 64 + c * 4]);
            acc[nn] = fmaf(a.x, x.x, acc[nn]);
            acc[nn] = fmaf(a.y, x.y, acc[nn]);
            acc[nn] = fmaf(a.z, x.z, acc[nn]);
            acc[nn] = fmaf(a.w, x.w, acc[nn]);
        }
    }
#pragma unroll
    for (int nn = 0; nn < 10; nn++)
        hs[nn * 64 + t] = fmaxf(acc[nn] + ba_i, 0.f);

    asm volatile("cp.async.wait_group 0;\n" ::: "memory");
    __syncthreads();

#pragma unroll
    for (int nn = 0; nn < 10; nn++) acc[nn] = 0.f;
#pragma unroll
    for (int c = 0; c < 16; c++) {
        float4 b = *reinterpret_cast<const float4*>(&B[t * 68 + c * 4]);
#pragma unroll
        for (int nn = 0; nn < 10; nn++) {
            float4 x = *reinterpret_cast<const float4*>(&hs[nn * 64 + c * 4]);
            acc[nn] = fmaf(b.x, x.x, acc[nn]);
            acc[nn] = fmaf(b.y, x.y, acc[nn]);
            acc[nn] = fmaf(b.z, x.z, acc[nn]);
            acc[nn] = fmaf(b.w, x.w, acc[nn]);
        }
    }
    float mx = acc[0];
#pragma unroll
    for (int nn = 1; nn < 10; nn++) mx = fmaxf(mx, acc[nn]);
    out[(size_t)s * 64 + t] = mx + bb_i;
}

// ---------- launch ----------
extern "C" void kernel_launch(void* const* d_in, const int* in_sizes, int n_in,
                              void* d_out, int out_size) {
    const float* cc0  = (const float*)d_in[0];
    const float* Wk   = (const float*)d_in[1];
    const float* bk   = (const float*)d_in[2];
    const float* Wq   = (const float*)d_in[3];
    const float* bq   = (const float*)d_in[4];
    const float* Wv   = (const float*)d_in[5];
    const float* bv   = (const float*)d_in[6];
    const float* cc_g = (const float*)d_in[7];
    const float* cc_b = (const float*)d_in[8];
    const float* W_ih = (const float*)d_in[9];
    const float* W_hh = (const float*)d_in[10];
    const float* b_ih = (const float*)d_in[11];
    const float* b_hh = (const float*)d_in[12];
    const float* ln_g = (const float*)d_in[13];
    const float* ln_b = (const float*)d_in[14];
    const float* W1   = (const float*)d_in[15];
    const float* b1   = (const float*)d_in[16];
    const float* W2   = (const float*)d_in[17];
    const float* b2   = (const float*)d_in[18];
    const float* Wa   = (const float*)d_in[19];
    const float* ba   = (const float*)d_in[20];
    const float* Wb   = (const float*)d_in[21];
    const float* bb   = (const float*)d_in[22];

    static int smem_set = 0;
    if (!smem_set) {
        cudaFuncSetAttribute(phase1_kernel,
                             cudaFuncAttributeMaxDynamicSharedMemorySize, DYN_BYTES);
        smem_set = 1;
    }

    phase1_kernel<<<1, 640, DYN_BYTES>>>(cc0, Wk, bk, Wq, bq, Wv, bv, cc_g, cc_b,
                                         W_ih, W_hh, b_ih, b_hh, ln_g, ln_b,
                                         W1, b1, W2, b2);
    phase2_kernel<<<NSLOT, 64>>>(Wa, ba, Wb, bb, (float*)d_out);
}